// round 5
// baseline (speedup 1.0000x reference)
#include <cuda_runtime.h>
#include <cstdint>
#include <math.h>

// ---------------------------------------------------------------------------
// SelectiveSSM, 2-kernel pipeline. B=4, L=1024, DM=64, DS=DI=128.
//   KA: block = 16 rows = 1 chunk. proj -> delta/Bm/C/gate; exp (MUFU) with
//       segment scan (4 steps/thread); emits cc, ch, P, Q. Last block runs
//       the 64-chunk prefix (former kb) -> H.
//   KC: y = sum_s(ch + cc*H), silu(gate), W_out GEMV, residual, LayerNorm.
// ---------------------------------------------------------------------------

#define NB    4
#define NL    1024
#define NROW  4096
#define NCH   64
#define TC    16
#define LOG2E 1.4426950408889634f

__device__ float g_gate[NROW * 128];
__device__ float g_cc  [NROW * 128];
__device__ float g_ch  [NROW * 128];
__device__ float g_P   [NB * NCH * 128];
__device__ float g_Q   [NB * NCH * 128];
__device__ float g_H   [NB * NCH * 128];
__device__ unsigned int g_count = 0;

__device__ __forceinline__ float ex2f(float v) {
    float r;
    asm("ex2.approx.ftz.f32 %0, %1;" : "=f"(r) : "f"(v));
    return r;
}
__device__ __forceinline__ float lg2f(float v) {
    float r;
    asm("lg2.approx.ftz.f32 %0, %1;" : "=f"(r) : "f"(v));
    return r;
}

// ---------------------------------------------------------------------------
// KA: 256 blocks x 512 threads, 3 blocks/SM target. smem ~34KB.
// ---------------------------------------------------------------------------
__global__ __launch_bounds__(512, 3) void ka(
    const float* __restrict__ x,   const float* __restrict__ Win,
    const float* __restrict__ Wd,  const float* __restrict__ bd,
    const float* __restrict__ WB,  const float* __restrict__ bB,
    const float* __restrict__ WC,  const float* __restrict__ bC,
    const float* __restrict__ A) {
    __shared__ __align__(16) float xs [TC * 64];
    __shared__ __align__(16) float dsm[TC * 128];   // delta * log2e
    __shared__ float bms [TC * 128];
    __shared__ float cs  [TC * 128];
    __shared__ float segP[4 * 128];
    __shared__ float segQ[4 * 128];
    __shared__ float psum[8 * 64];
    __shared__ float wpool[64];
    __shared__ float pools[TC];
    __shared__ int   isLast;

    int tid = threadIdx.x;
    int row0 = blockIdx.x * TC;

    // phase 0: x rows + wpool partial column sums
    for (int i = tid; i < TC * 64; i += 512) xs[i] = x[row0 * 64 + i];
    {
        int d = tid & 63, part = tid >> 6;
        float s = 0.f;
        const float* p = Win + part * 16 * 64 + d;
#pragma unroll
        for (int i = 0; i < 16; i++) s += p[i * 64];
        psum[part * 64 + d] = s;
    }
    __syncthreads();

    if (tid < 64) {
        float s = 0.f;
#pragma unroll
        for (int p = 0; p < 8; p++) s += psum[p * 64 + tid];
        wpool[tid] = s * (1.0f / 128.0f);
    }

    // phase 1: projections, two 8-row passes (acc[8] keeps regs low)
    int mode = tid >> 7, fo = tid & 127;
    const float* wrow;
    float bias = 0.f;
    if (mode == 0)      { wrow = Win + (128 + fo) * 64; }
    else if (mode == 1) { wrow = Wd + fo * 64; bias = bd[fo]; }
    else if (mode == 2) { wrow = WB + fo * 64; bias = bB[fo]; }
    else                { wrow = WC + fo * 64; bias = bC[fo]; }
    const float4* w4 = (const float4*)wrow;

#pragma unroll
    for (int half = 0; half < 2; half++) {
        float acc[8];
#pragma unroll
        for (int r = 0; r < 8; r++) acc[r] = 0.f;
#pragma unroll
        for (int d4 = 0; d4 < 16; d4++) {
            float4 wv = __ldg(&w4[d4]);
#pragma unroll
            for (int r = 0; r < 8; r++) {
                float4 xv = *(const float4*)(xs + (half * 8 + r) * 64 + d4 * 4);
                acc[r] = fmaf(wv.x, xv.x, acc[r]);
                acc[r] = fmaf(wv.y, xv.y, acc[r]);
                acc[r] = fmaf(wv.z, xv.z, acc[r]);
                acc[r] = fmaf(wv.w, xv.w, acc[r]);
            }
        }
#pragma unroll
        for (int r = 0; r < 8; r++) {
            int rr = half * 8 + r;
            float v = acc[r] + bias;
            if (mode == 0)      g_gate[(row0 + rr) * 128 + fo] = v;
            else if (mode == 1) dsm[rr * 128 + fo] = lg2f(1.0f + ex2f(v * LOG2E));
            else if (mode == 2) bms[rr * 128 + fo] = v;
            else                cs [rr * 128 + fo] = v;
        }
    }
    __syncthreads();   // dsm, bms, cs, wpool published

    // x_pool (tiny; published by the sync after the exp phase)
    if (tid < TC) {
        float p = 0.f;
#pragma unroll
        for (int d = 0; d < 64; d++) p = fmaf(wpool[d], xs[tid * 64 + d], p);
        pools[tid] = p;
    }

    // phase 2: exp sums. thread (s, rq) owns rows rq*4..rq*4+3.
    int s = tid & 127, rq = tid >> 7;
    float a[4];
    {
        const float* dr = dsm + rq * 4 * 128;
        float s0 = 0.f, s1 = 0.f, s2 = 0.f, s3 = 0.f;
#pragma unroll 4
        for (int i = 0; i < 128; i += 4) {
            float4 q0 = *(const float4*)(dr + i);
            float4 q1 = *(const float4*)(dr + 128 + i);
            float4 q2 = *(const float4*)(dr + 256 + i);
            float4 q3 = *(const float4*)(dr + 384 + i);
            float A0 = __ldg(A + (i + 0) * 128 + s);
            float A1 = __ldg(A + (i + 1) * 128 + s);
            float A2 = __ldg(A + (i + 2) * 128 + s);
            float A3 = __ldg(A + (i + 3) * 128 + s);
            s0 += (ex2f(q0.x * A0) + ex2f(q0.y * A1)) + (ex2f(q0.z * A2) + ex2f(q0.w * A3));
            s1 += (ex2f(q1.x * A0) + ex2f(q1.y * A1)) + (ex2f(q1.z * A2) + ex2f(q1.w * A3));
            s2 += (ex2f(q2.x * A0) + ex2f(q2.y * A1)) + (ex2f(q2.z * A2) + ex2f(q2.w * A3));
            s3 += (ex2f(q3.x * A0) + ex2f(q3.y * A1)) + (ex2f(q3.z * A2) + ex2f(q3.w * A3));
        }
        a[0] = s0 * (1.0f / 128.0f);
        a[1] = s1 * (1.0f / 128.0f);
        a[2] = s2 * (1.0f / 128.0f);
        a[3] = s3 * (1.0f / 128.0f);
    }
    __syncthreads();   // pools ready (exp work done)

    // segment scan over this thread's 4 timesteps
    float bp[4];
    {
        float h = 0.f, cA = 1.f;
#pragma unroll
        for (int k = 0; k < 4; k++) {
            int t = rq * 4 + k;
            bp[k] = bms[t * 128 + s] * pools[t];
            h = fmaf(a[k], h, bp[k]);
            cA *= a[k];
        }
        segP[rq * 128 + s] = cA;
        segQ[rq * 128 + s] = h;
    }
    __syncthreads();

    // phase 3: fold preceding segments, emit cc/ch for own 4 steps
    {
        float Pp = 1.f, h = 0.f;
#pragma unroll
        for (int j = 0; j < 3; j++) {
            if (j < rq) {
                float pj = segP[j * 128 + s];
                h = fmaf(pj, h, segQ[j * 128 + s]);
                Pp *= pj;
            }
        }
#pragma unroll
        for (int k = 0; k < 4; k++) {
            int t = rq * 4 + k;
            h = fmaf(a[k], h, bp[k]);
            Pp *= a[k];
            float c = cs[t * 128 + s];
            int off = (row0 + t) * 128 + s;
            g_cc[off] = c * Pp;
            g_ch[off] = c * h;
        }
        if (rq == 3) {
            g_P[blockIdx.x * 128 + s] = Pp;
            g_Q[blockIdx.x * 128 + s] = h;
        }
    }

    // last-block-done: run the 64-chunk prefix (former kb)
    __threadfence();
    __syncthreads();
    if (tid == 0) {
        unsigned int old = atomicAdd(&g_count, 1u);
        isLast = (old == (unsigned)(gridDim.x - 1));
    }
    __syncthreads();
    if (isLast) {
        __threadfence();
        int b = tid >> 7, ss = tid & 127;
        int o0 = b * NCH * 128 + ss;
        float P[2][8], Q[2][8];
#pragma unroll
        for (int j = 0; j < 8; j++) {
            P[0][j] = g_P[o0 + j * 128];
            Q[0][j] = g_Q[o0 + j * 128];
        }
        float H = 0.f;
        for (int T = 0; T < 8; T++) {
            int cur = T & 1, nxt = cur ^ 1;
            if (T < 7) {
#pragma unroll
                for (int j = 0; j < 8; j++) {
                    int o = o0 + ((T + 1) * 8 + j) * 128;
                    P[nxt][j] = g_P[o];
                    Q[nxt][j] = g_Q[o];
                }
            }
#pragma unroll
            for (int j = 0; j < 8; j++) {
                g_H[o0 + (T * 8 + j) * 128] = H;
                H = fmaf(P[cur][j], H, Q[cur][j]);
            }
        }
        if (tid == 0) g_count = 0;   // reset for graph replay
    }
}

// ---------------------------------------------------------------------------
// KC: 256 blocks x 256 threads. y = sum(ch + cc*H), silu, GEMV, LN.
// ---------------------------------------------------------------------------
__global__ __launch_bounds__(256) void kc(const float* __restrict__ x,
                                          const float* __restrict__ Wout,
                                          const float* __restrict__ lnw,
                                          const float* __restrict__ lnb,
                                          float* __restrict__ out) {
    __shared__ float WT2s[128 * 65];
    __shared__ float yis[TC * 128];
    __shared__ float Hs[128];
    int tid = threadIdx.x, lane = tid & 31, w = tid >> 5;
    int row0 = blockIdx.x * TC;

    for (int lin = tid; lin < 8192; lin += 256) {
        int d = lin >> 7, ii = lin & 127;
        WT2s[ii * 65 + d] = Wout[lin];
    }
    if (tid < 128) Hs[tid] = g_H[blockIdx.x * 128 + tid];
    __syncthreads();

#pragma unroll
    for (int rr = 0; rr < 2; rr++) {
        int r = w * 2 + rr;
        int row = row0 + r;
        float acc = 0.f;
        float gt[4];
#pragma unroll
        for (int q = 0; q < 4; q++) {
            int s = lane + q * 32;
            int off = row * 128 + s;
            acc += g_ch[off] + g_cc[off] * Hs[s];
            gt[q] = g_gate[off];
        }
#pragma unroll
        for (int o = 16; o > 0; o >>= 1) acc += __shfl_xor_sync(0xffffffffu, acc, o);
#pragma unroll
        for (int q = 0; q < 4; q++) {
            int s = lane + q * 32;
            float sig = 1.0f / (1.0f + __expf(-gt[q]));
            yis[r * 128 + s] = acc * gt[q] * sig;
        }
    }
    __syncthreads();

#pragma unroll
    for (int rr = 0; rr < 2; rr++) {
        int r = w * 2 + rr;
        int row = row0 + r;
        float acc0 = 0.f, acc1 = 0.f;
#pragma unroll
        for (int i = 0; i < 128; i++) {
            float yv = yis[r * 128 + i];
            acc0 = fmaf(WT2s[i * 65 + lane],      yv, acc0);
            acc1 = fmaf(WT2s[i * 65 + lane + 32], yv, acc1);
        }
        float v0 = acc0 + x[row * 64 + lane];
        float v1 = acc1 + x[row * 64 + lane + 32];
        float sv = v0 + v1, sq = v0 * v0 + v1 * v1;
#pragma unroll
        for (int o = 16; o > 0; o >>= 1) {
            sv += __shfl_xor_sync(0xffffffffu, sv, o);
            sq += __shfl_xor_sync(0xffffffffu, sq, o);
        }
        float mu  = sv * (1.0f / 64.0f);
        float var = sq * (1.0f / 64.0f) - mu * mu;
        float inv = rsqrtf(var + 1e-5f);
        out[row * 64 + lane]      = (v0 - mu) * inv * lnw[lane]      + lnb[lane];
        out[row * 64 + lane + 32] = (v1 - mu) * inv * lnw[lane + 32] + lnb[lane + 32];
    }
}

// ---------------------------------------------------------------------------
extern "C" void kernel_launch(void* const* d_in, const int* in_sizes, int n_in,
                              void* d_out, int out_size) {
    const float* x    = (const float*)d_in[0];
    const float* Win  = (const float*)d_in[1];
    const float* Wd   = (const float*)d_in[2];
    const float* bd   = (const float*)d_in[3];
    const float* WB   = (const float*)d_in[4];
    const float* bB   = (const float*)d_in[5];
    const float* WC   = (const float*)d_in[6];
    const float* bC   = (const float*)d_in[7];
    const float* A    = (const float*)d_in[8];
    const float* Wout = (const float*)d_in[9];
    const float* lnw  = (const float*)d_in[10];
    const float* lnb  = (const float*)d_in[11];
    float* out = (float*)d_out;

    ka<<<NROW / TC, 512>>>(x, Win, Wd, bd, WB, bB, WC, bC, A);
    kc<<<NROW / TC, 256>>>(x, Wout, lnw, lnb, out);
}

// round 6
// speedup vs baseline: 1.2052x; 1.2052x over previous
#include <cuda_runtime.h>
#include <cstdint>
#include <math.h>

// ---------------------------------------------------------------------------
// SelectiveSSM, 3-kernel pipeline. B=4, L=1024, DM=64, DS=DI=128.
//   KA: block = 16 rows = 1 chunk. proj -> delta/Bm/C/gate; exp (MUFU) with
//       A staged in smem; segment scan (4 steps/thread); emits cc, ch, P, Q.
//   KB: 1 block: 64-chunk prefix scan of (P,Q) -> H.
//   KC: warp-per-row: y = sum_s(ch + cc*H), silu(gate), W_out GEMV,
//       residual, LayerNorm.
// ---------------------------------------------------------------------------

#define NB    4
#define NL    1024
#define NROW  4096
#define NCH   64
#define TC    16
#define LOG2E 1.4426950408889634f

__device__ float g_gate[NROW * 128];
__device__ float g_cc  [NROW * 128];
__device__ float g_ch  [NROW * 128];
__device__ float g_P   [NB * NCH * 128];
__device__ float g_Q   [NB * NCH * 128];
__device__ float g_H   [NB * NCH * 128];

__device__ __forceinline__ float ex2f(float v) {
    float r;
    asm("ex2.approx.ftz.f32 %0, %1;" : "=f"(r) : "f"(v));
    return r;
}
__device__ __forceinline__ float lg2f(float v) {
    float r;
    asm("lg2.approx.ftz.f32 %0, %1;" : "=f"(r) : "f"(v));
    return r;
}

// dynamic smem layout for KA (floats):
//   Asm[16384] | xs[1024] | dsm[2048] | bms[2048] | cs[2048] |
//   segP[512] | segQ[512] | psum[512] | wpool[64] | pools[16]
#define KA_SMEM_FLOATS (16384 + 1024 + 2048 + 2048 + 2048 + 512 + 512 + 512 + 64 + 16)

// ---------------------------------------------------------------------------
// KA: 256 blocks x 512 threads, 2 blocks/SM (reg-capped). smem ~98KB.
// ---------------------------------------------------------------------------
__global__ __launch_bounds__(512, 2) void ka(
    const float* __restrict__ x,   const float* __restrict__ Win,
    const float* __restrict__ Wd,  const float* __restrict__ bd,
    const float* __restrict__ WB,  const float* __restrict__ bB,
    const float* __restrict__ WC,  const float* __restrict__ bC,
    const float* __restrict__ A) {
    extern __shared__ __align__(16) float sm[];
    float* Asm   = sm;
    float* xs    = Asm + 16384;
    float* dsm   = xs + 1024;
    float* bms   = dsm + 2048;
    float* cs    = bms + 2048;
    float* segP  = cs + 2048;
    float* segQ  = segP + 512;
    float* psum  = segQ + 512;
    float* wpool = psum + 512;
    float* pools = wpool + 64;

    int tid = threadIdx.x;
    int row0 = blockIdx.x * TC;

    // phase 0: stage A (float4), x rows, wpool partial column sums
    {
        const float4* A4 = (const float4*)A;
        float4* Asm4 = (float4*)Asm;
        for (int i = tid; i < 4096; i += 512) Asm4[i] = A4[i];
    }
    for (int i = tid; i < TC * 64; i += 512) xs[i] = x[row0 * 64 + i];
    {
        int d = tid & 63, part = tid >> 6;
        float s = 0.f;
        const float* p = Win + part * 16 * 64 + d;
#pragma unroll
        for (int i = 0; i < 16; i++) s += p[i * 64];
        psum[part * 64 + d] = s;
    }
    __syncthreads();

    if (tid < 64) {
        float s = 0.f;
#pragma unroll
        for (int p = 0; p < 8; p++) s += psum[p * 64 + tid];
        wpool[tid] = s * (1.0f / 128.0f);
    }

    // phase 1: projections (thread = feature, 16 row-accumulators)
    int mode = tid >> 7, fo = tid & 127;
    const float* wrow;
    float bias = 0.f;
    if (mode == 0)      { wrow = Win + (128 + fo) * 64; }
    else if (mode == 1) { wrow = Wd + fo * 64; bias = bd[fo]; }
    else if (mode == 2) { wrow = WB + fo * 64; bias = bB[fo]; }
    else                { wrow = WC + fo * 64; bias = bC[fo]; }
    const float4* w4 = (const float4*)wrow;

    float acc[TC];
#pragma unroll
    for (int r = 0; r < TC; r++) acc[r] = 0.f;
#pragma unroll
    for (int d4 = 0; d4 < 16; d4++) {
        float4 wv = __ldg(&w4[d4]);
#pragma unroll
        for (int r = 0; r < TC; r++) {
            float4 xv = *(const float4*)(xs + r * 64 + d4 * 4);
            acc[r] = fmaf(wv.x, xv.x, acc[r]);
            acc[r] = fmaf(wv.y, xv.y, acc[r]);
            acc[r] = fmaf(wv.z, xv.z, acc[r]);
            acc[r] = fmaf(wv.w, xv.w, acc[r]);
        }
    }
#pragma unroll
    for (int r = 0; r < TC; r++) {
        float v = acc[r] + bias;
        if (mode == 0)      g_gate[(row0 + r) * 128 + fo] = v;
        else if (mode == 1) dsm[r * 128 + fo] = lg2f(1.0f + ex2f(v * LOG2E));
        else if (mode == 2) bms[r * 128 + fo] = v;
        else                cs [r * 128 + fo] = v;
    }
    __syncthreads();   // dsm, bms, cs, wpool, Asm published

    // x_pool (published by the sync after the exp phase)
    if (tid < TC) {
        float p = 0.f;
#pragma unroll
        for (int d = 0; d < 64; d++) p = fmaf(wpool[d], xs[tid * 64 + d], p);
        pools[tid] = p;
    }

    // phase 2: exp sums. thread (s, rq) owns rows rq*4..rq*4+3.
    //   delta reads: warp-broadcast LDS.128. A reads: stride-1 LDS.32.
    int s = tid & 127, rq = tid >> 7;
    float a[4];
    {
        const float* dr = dsm + rq * 4 * 128;
        float s0 = 0.f, s1 = 0.f, s2 = 0.f, s3 = 0.f;
#pragma unroll 4
        for (int i = 0; i < 128; i += 4) {
            float4 q0 = *(const float4*)(dr + i);
            float4 q1 = *(const float4*)(dr + 128 + i);
            float4 q2 = *(const float4*)(dr + 256 + i);
            float4 q3 = *(const float4*)(dr + 384 + i);
            float A0 = Asm[(i + 0) * 128 + s];
            float A1 = Asm[(i + 1) * 128 + s];
            float A2 = Asm[(i + 2) * 128 + s];
            float A3 = Asm[(i + 3) * 128 + s];
            s0 += (ex2f(q0.x * A0) + ex2f(q0.y * A1)) + (ex2f(q0.z * A2) + ex2f(q0.w * A3));
            s1 += (ex2f(q1.x * A0) + ex2f(q1.y * A1)) + (ex2f(q1.z * A2) + ex2f(q1.w * A3));
            s2 += (ex2f(q2.x * A0) + ex2f(q2.y * A1)) + (ex2f(q2.z * A2) + ex2f(q2.w * A3));
            s3 += (ex2f(q3.x * A0) + ex2f(q3.y * A1)) + (ex2f(q3.z * A2) + ex2f(q3.w * A3));
        }
        a[0] = s0 * (1.0f / 128.0f);
        a[1] = s1 * (1.0f / 128.0f);
        a[2] = s2 * (1.0f / 128.0f);
        a[3] = s3 * (1.0f / 128.0f);
    }
    __syncthreads();   // pools ready

    // segment scan over this thread's 4 timesteps
    float bp[4];
    {
        float h = 0.f, cA = 1.f;
#pragma unroll
        for (int k = 0; k < 4; k++) {
            int t = rq * 4 + k;
            bp[k] = bms[t * 128 + s] * pools[t];
            h = fmaf(a[k], h, bp[k]);
            cA *= a[k];
        }
        segP[rq * 128 + s] = cA;
        segQ[rq * 128 + s] = h;
    }
    __syncthreads();

    // phase 3: fold preceding segments, emit cc/ch for own 4 steps
    {
        float Pp = 1.f, h = 0.f;
#pragma unroll
        for (int j = 0; j < 3; j++) {
            if (j < rq) {
                float pj = segP[j * 128 + s];
                h = fmaf(pj, h, segQ[j * 128 + s]);
                Pp *= pj;
            }
        }
#pragma unroll
        for (int k = 0; k < 4; k++) {
            int t = rq * 4 + k;
            h = fmaf(a[k], h, bp[k]);
            Pp *= a[k];
            float c = cs[t * 128 + s];
            int off = (row0 + t) * 128 + s;
            g_cc[off] = c * Pp;
            g_ch[off] = c * h;
        }
        if (rq == 3) {
            g_P[blockIdx.x * 128 + s] = Pp;
            g_Q[blockIdx.x * 128 + s] = h;
        }
    }
}

// ---------------------------------------------------------------------------
// KB: 1 block, 512 threads: (b = tid>>7, s = tid&127), 64-chunk serial scan.
// ---------------------------------------------------------------------------
__global__ void kb() {
    int tid = threadIdx.x;
    int b = tid >> 7, s = tid & 127;
    int o0 = b * NCH * 128 + s;
    float P[2][8], Q[2][8];
#pragma unroll
    for (int j = 0; j < 8; j++) {
        P[0][j] = g_P[o0 + j * 128];
        Q[0][j] = g_Q[o0 + j * 128];
    }
    float H = 0.f;
    for (int T = 0; T < 8; T++) {
        int cur = T & 1, nxt = cur ^ 1;
        if (T < 7) {
#pragma unroll
            for (int j = 0; j < 8; j++) {
                int o = o0 + ((T + 1) * 8 + j) * 128;
                P[nxt][j] = g_P[o];
                Q[nxt][j] = g_Q[o];
            }
        }
#pragma unroll
        for (int j = 0; j < 8; j++) {
            g_H[o0 + (T * 8 + j) * 128] = H;
            H = fmaf(P[cur][j], H, Q[cur][j]);
        }
    }
}

// ---------------------------------------------------------------------------
// KC: 256 blocks x 512 threads, warp-per-row. Bounded unroll -> low regs.
// ---------------------------------------------------------------------------
__global__ __launch_bounds__(512) void kc(const float* __restrict__ x,
                                          const float* __restrict__ Wout,
                                          const float* __restrict__ lnw,
                                          const float* __restrict__ lnb,
                                          float* __restrict__ out) {
    __shared__ float WT2s[128 * 65];
    __shared__ float yis[TC * 128];
    __shared__ float Hs[128];
    int tid = threadIdx.x, lane = tid & 31, w = tid >> 5;
    int row0 = blockIdx.x * TC;

    for (int lin = tid; lin < 8192; lin += 512) {
        int d = lin >> 7, ii = lin & 127;
        WT2s[ii * 65 + d] = Wout[lin];
    }
    if (tid < 128) Hs[tid] = g_H[blockIdx.x * 128 + tid];
    __syncthreads();

    int row = row0 + w;

    // phase A: warp w reduces y for row w, writes yi = y*silu(gate)
    {
        float acc = 0.f;
        float gt[4];
#pragma unroll
        for (int q = 0; q < 4; q++) {
            int s = lane + q * 32;
            int off = row * 128 + s;
            acc += g_ch[off] + g_cc[off] * Hs[s];
            gt[q] = g_gate[off];
        }
#pragma unroll
        for (int o = 16; o > 0; o >>= 1) acc += __shfl_xor_sync(0xffffffffu, acc, o);
#pragma unroll
        for (int q = 0; q < 4; q++) {
            int s = lane + q * 32;
            float sig = 1.0f / (1.0f + __expf(-gt[q]));
            yis[w * 128 + s] = acc * gt[q] * sig;
        }
    }
    __syncthreads();

    // phase B: GEMV + residual + warp-private LayerNorm (d = lane, lane+32)
    {
        float acc0 = 0.f, acc1 = 0.f;
#pragma unroll 8
        for (int i = 0; i < 128; i++) {
            float yv = yis[w * 128 + i];
            acc0 = fmaf(WT2s[i * 65 + lane],      yv, acc0);
            acc1 = fmaf(WT2s[i * 65 + lane + 32], yv, acc1);
        }
        float v0 = acc0 + x[row * 64 + lane];
        float v1 = acc1 + x[row * 64 + lane + 32];
        float sv = v0 + v1, sq = v0 * v0 + v1 * v1;
#pragma unroll
        for (int o = 16; o > 0; o >>= 1) {
            sv += __shfl_xor_sync(0xffffffffu, sv, o);
            sq += __shfl_xor_sync(0xffffffffu, sq, o);
        }
        float mu  = sv * (1.0f / 64.0f);
        float var = sq * (1.0f / 64.0f) - mu * mu;
        float inv = rsqrtf(var + 1e-5f);
        out[row * 64 + lane]      = (v0 - mu) * inv * lnw[lane]      + lnb[lane];
        out[row * 64 + lane + 32] = (v1 - mu) * inv * lnw[lane + 32] + lnb[lane + 32];
    }
}

// ---------------------------------------------------------------------------
extern "C" void kernel_launch(void* const* d_in, const int* in_sizes, int n_in,
                              void* d_out, int out_size) {
    const float* x    = (const float*)d_in[0];
    const float* Win  = (const float*)d_in[1];
    const float* Wd   = (const float*)d_in[2];
    const float* bd   = (const float*)d_in[3];
    const float* WB   = (const float*)d_in[4];
    const float* bB   = (const float*)d_in[5];
    const float* WC   = (const float*)d_in[6];
    const float* bC   = (const float*)d_in[7];
    const float* A    = (const float*)d_in[8];
    const float* Wout = (const float*)d_in[9];
    const float* lnw  = (const float*)d_in[10];
    const float* lnb  = (const float*)d_in[11];
    float* out = (float*)d_out;

    cudaFuncSetAttribute(ka, cudaFuncAttributeMaxDynamicSharedMemorySize,
                         KA_SMEM_FLOATS * (int)sizeof(float));

    ka<<<NROW / TC, 512, KA_SMEM_FLOATS * sizeof(float)>>>(
        x, Win, Wd, bd, WB, bB, WC, bC, A);
    kb<<<1, 512>>>();
    kc<<<NROW / TC, 512>>>(x, Wout, lnw, lnb, out);
}